// round 5
// baseline (speedup 1.0000x reference)
#include <cuda_runtime.h>
#include <cstdint>

#define EPS 1e-5f

// ---------------- scratch (device globals: no allocation allowed) ----------
__device__ float g_xemb[256 * 256 * 256];   // [b][c][d]  64 Mi floats
__device__ float g_xpin[256 * 512];          // [p][ln_prompt | prev_cell_out]
__device__ float g_xprompt[256 * 256];       // [p][d]
__device__ float g_xcol[256 * 256];          // [c][d]
__device__ float g_logits[256 * 256];        // [p][c]
__device__ float g_mask[256 * 256];          // [p][c] softmax

// ---------------- f32x2 helpers (sm_103a packed fp32 pipe) ------------------
__device__ __forceinline__ unsigned long long pack2(float lo, float hi) {
    unsigned long long r;
    asm("mov.b64 %0, {%1, %2};" : "=l"(r) : "f"(lo), "f"(hi));
    return r;
}
__device__ __forceinline__ unsigned long long dup2(float v) {
    unsigned long long r;
    asm("mov.b64 %0, {%1, %1};" : "=l"(r) : "f"(v));
    return r;
}
__device__ __forceinline__ void fma2(unsigned long long& acc,
                                     unsigned long long a, unsigned long long b) {
    asm("fma.rn.f32x2 %0, %1, %2, %0;" : "+l"(acc) : "l"(a), "l"(b));
}
__device__ __forceinline__ void unpack2(unsigned long long v, float& lo, float& hi) {
    asm("mov.b64 {%0, %1}, %2;" : "=f"(lo), "=f"(hi) : "l"(v));
}

// ---------------- warp-per-row LayerNorm helper -----------------------------
__device__ __forceinline__ void ln_row_warp(const float4 v0, const float4 v1,
                                            const float* __restrict__ w,
                                            const float* __restrict__ b,
                                            float* __restrict__ dst, int lane) {
    float s = v0.x + v0.y + v0.z + v0.w + v1.x + v1.y + v1.z + v1.w;
    float q = v0.x * v0.x + v0.y * v0.y + v0.z * v0.z + v0.w * v0.w +
              v1.x * v1.x + v1.y * v1.y + v1.z * v1.z + v1.w * v1.w;
#pragma unroll
    for (int o = 16; o; o >>= 1) {
        s += __shfl_xor_sync(0xffffffffu, s, o);
        q += __shfl_xor_sync(0xffffffffu, q, o);
    }
    float mu = s * (1.0f / 256.0f);
    float rs = rsqrtf(q * (1.0f / 256.0f) - mu * mu + EPS);
    const float4* w4 = reinterpret_cast<const float4*>(w);
    const float4* b4 = reinterpret_cast<const float4*>(b);
    float4 g0 = w4[lane], g1 = w4[lane + 32];
    float4 h0 = b4[lane], h1 = b4[lane + 32];
    float4 o0, o1;
    o0.x = (v0.x - mu) * rs * g0.x + h0.x;
    o0.y = (v0.y - mu) * rs * g0.y + h0.y;
    o0.z = (v0.z - mu) * rs * g0.z + h0.z;
    o0.w = (v0.w - mu) * rs * g0.w + h0.w;
    o1.x = (v1.x - mu) * rs * g1.x + h1.x;
    o1.y = (v1.y - mu) * rs * g1.y + h1.y;
    o1.z = (v1.z - mu) * rs * g1.z + h1.z;
    o1.w = (v1.w - mu) * rs * g1.w + h1.w;
    float4* d4 = reinterpret_cast<float4*>(dst);
    d4[lane] = o0;
    d4[lane + 32] = o1;
}

// ---------------- kernel 1: x_emb = LN(relu(fb + x*fw)) ---------------------
__global__ void __launch_bounds__(256) k_xemb(const float* __restrict__ x,
                                              const float* __restrict__ fw,
                                              const float* __restrict__ fb,
                                              const float* __restrict__ lw,
                                              const float* __restrict__ lb) {
    int row = blockIdx.x * 8 + (threadIdx.x >> 5);  // row = b*256 + c
    int lane = threadIdx.x & 31;
    int c = row & 255;
    float xv = x[row];
    const float4* fw4 = reinterpret_cast<const float4*>(fw) + c * 64;
    const float4* fb4 = reinterpret_cast<const float4*>(fb) + c * 64;
    float4 w0 = fw4[lane], w1 = fw4[lane + 32];
    float4 a0 = fb4[lane], a1 = fb4[lane + 32];
    float4 v0, v1;
    v0.x = fmaxf(fmaf(xv, w0.x, a0.x), 0.0f);
    v0.y = fmaxf(fmaf(xv, w0.y, a0.y), 0.0f);
    v0.z = fmaxf(fmaf(xv, w0.z, a0.z), 0.0f);
    v0.w = fmaxf(fmaf(xv, w0.w, a0.w), 0.0f);
    v1.x = fmaxf(fmaf(xv, w1.x, a1.x), 0.0f);
    v1.y = fmaxf(fmaf(xv, w1.y, a1.y), 0.0f);
    v1.z = fmaxf(fmaf(xv, w1.z, a1.z), 0.0f);
    v1.w = fmaxf(fmaf(xv, w1.w, a1.w), 0.0f);
    ln_row_warp(v0, v1, lw, lb, g_xemb + (size_t)row * 256, lane);
}

// ---------------- kernel 2: LN(emb_prompt)->xpin, copy prev, LN(emb_col) ----
__global__ void __launch_bounds__(256) k_prep(const float* __restrict__ eprm,
                                              const float* __restrict__ prev,
                                              const float* __restrict__ lpw,
                                              const float* __restrict__ lpb,
                                              const float* __restrict__ ecol,
                                              const float* __restrict__ lcw,
                                              const float* __restrict__ lcb) {
    int row = blockIdx.x * 8 + (threadIdx.x >> 5);  // 0..511
    int lane = threadIdx.x & 31;
    if (row < 256) {
        const float4* s4 = reinterpret_cast<const float4*>(eprm) + row * 64;
        ln_row_warp(s4[lane], s4[lane + 32], lpw, lpb, g_xpin + row * 512, lane);
        const float4* p4 = reinterpret_cast<const float4*>(prev) + row * 64;
        float4* d4 = reinterpret_cast<float4*>(g_xpin + row * 512 + 256);
        d4[lane] = p4[lane];
        d4[lane + 32] = p4[lane + 32];
    } else {
        int c = row - 256;
        const float4* s4 = reinterpret_cast<const float4*>(ecol) + c * 64;
        ln_row_warp(s4[lane], s4[lane + 32], lcw, lcb, g_xcol + c * 256, lane);
    }
}

// ---------------- kernel 3: small GEMMs  out[i,j] = sum_k A[i,k]*B[j,k] ----
// MODE 0: x_prompt = xpin(512) @ W.T + bias + emb_prompt
// MODE 1: logits   = x_prompt(256) @ x_col.T
template <int MODE>
__global__ void __launch_bounds__(256) k_gemm(const float* __restrict__ Bp,
                                              const float* __restrict__ bias,
                                              const float* __restrict__ add) {
    constexpr int K = (MODE == 0) ? 512 : 256;
    const float* A = (MODE == 0) ? g_xpin : g_xprompt;
    const float* B = (MODE == 0) ? Bp : g_xcol;
    float* C = (MODE == 0) ? g_xprompt : g_logits;

    __shared__ float sA[32][65];
    __shared__ float sB[32][65];
    int tid = threadIdx.x;
    int i0 = blockIdx.y * 32, j0 = blockIdx.x * 32;
    int ty = tid >> 4, tx = tid & 15;
    float acc00 = 0.f, acc01 = 0.f, acc10 = 0.f, acc11 = 0.f;

    for (int kc = 0; kc < K; kc += 64) {
#pragma unroll
        for (int t = 0; t < 8; t++) {
            int flat = tid + t * 256;        // 0..2047
            int r = flat >> 6, kk = flat & 63;
            sA[r][kk] = A[(i0 + r) * K + kc + kk];
            sB[r][kk] = B[(j0 + r) * K + kc + kk];
        }
        __syncthreads();
#pragma unroll 8
        for (int k = 0; k < 64; k++) {
            float a0 = sA[ty * 2][k], a1 = sA[ty * 2 + 1][k];
            float b0 = sB[tx * 2][k], b1 = sB[tx * 2 + 1][k];
            acc00 = fmaf(a0, b0, acc00);
            acc01 = fmaf(a0, b1, acc01);
            acc10 = fmaf(a1, b0, acc10);
            acc11 = fmaf(a1, b1, acc11);
        }
        __syncthreads();
    }
    int i = i0 + ty * 2, j = j0 + tx * 2;
    float e00 = acc00, e01 = acc01, e10 = acc10, e11 = acc11;
    if (MODE == 0) {
        e00 += bias[j] + add[i * 256 + j];
        e01 += bias[j + 1] + add[i * 256 + j + 1];
        e10 += bias[j] + add[(i + 1) * 256 + j];
        e11 += bias[j + 1] + add[(i + 1) * 256 + j + 1];
    }
    C[i * 256 + j] = e00;
    C[i * 256 + j + 1] = e01;
    C[(i + 1) * 256 + j] = e10;
    C[(i + 1) * 256 + j + 1] = e11;
}

// ---------------- kernel 4: row softmax  mask = softmax(logits, axis=c) -----
__global__ void __launch_bounds__(256) k_softmax() {
    __shared__ float red[256];
    int p = blockIdx.x, c = threadIdx.x;
    float v = g_logits[p * 256 + c];
    red[c] = v;
    __syncthreads();
#pragma unroll
    for (int s = 128; s > 0; s >>= 1) {
        if (c < s) red[c] = fmaxf(red[c], red[c + s]);
        __syncthreads();
    }
    float mx = red[0];
    __syncthreads();
    float e = expf(v - mx);
    red[c] = e;
    __syncthreads();
#pragma unroll
    for (int s = 128; s > 0; s >>= 1) {
        if (c < s) red[c] += red[c + s];
        __syncthreads();
    }
    g_mask[p * 256 + c] = e * (1.0f / red[0]);
}

// ---------------- kernel 5: out[b,p,d] = (1+ew[p])*sum_c mask[p,c]*xemb[b,c,d]
//                                         + mask[b,p]*eb[b]
// FFMA2 (fma.rn.f32x2) GEMM: 128x128 tile per CTA, 8x8 per thread, TK=32.
// mask tile stored k-major so adjacent-p pairs are naturally b64-packed.
__global__ void __launch_bounds__(256) k_main(const float* __restrict__ ew,
                                              const float* __restrict__ eb,
                                              float* __restrict__ out) {
    __shared__ float sA[32][132];  // [k][p]  (132*4B row -> 16B aligned, conflict-spread)
    __shared__ float sX[32][128];  // [k][d]
    int tid = threadIdx.x;
    int b = blockIdx.z;
    int p0 = blockIdx.y * 128, d0 = blockIdx.x * 128;
    int tx = tid & 15, ty = tid >> 4;
    int pr = ty * 4, dr = tx * 4;

    unsigned long long acc[4][8];
#pragma unroll
    for (int i = 0; i < 4; i++)
#pragma unroll
        for (int j = 0; j < 8; j++) acc[i][j] = 0ull;

    const float* xe = g_xemb + (size_t)b * 65536;

    for (int kc = 0; kc < 256; kc += 32) {
        // mask tile: rows p0..p0+127 x k kc..kc+31, transposed into sA[k][p]
#pragma unroll
        for (int i = 0; i < 4; i++) {
            int idx = tid + i * 256;       // 0..1023 float4 slots
            int row = idx >> 3;            // 8 float4 per mask row
            int c4 = idx & 7;
            float4 v = *reinterpret_cast<const float4*>(
                &g_mask[(p0 + row) * 256 + kc + c4 * 4]);
            sA[c4 * 4 + 0][row] = v.x;
            sA[c4 * 4 + 1][row] = v.y;
            sA[c4 * 4 + 2][row] = v.z;
            sA[c4 * 4 + 3][row] = v.w;
        }
        // xemb tile: 32 k-rows x 128 d, direct
#pragma unroll
        for (int i = 0; i < 4; i++) {
            int idx = tid + i * 256;
            int row = idx >> 5;            // 32 float4 per row
            int c4 = idx & 31;
            *reinterpret_cast<float4*>(&sX[row][c4 * 4]) =
                *reinterpret_cast<const float4*>(&xe[(kc + row) * 256 + d0 + c4 * 4]);
        }
        __syncthreads();
#pragma unroll
        for (int k = 0; k < 32; k++) {
            float4 alo = *reinterpret_cast<const float4*>(&sA[k][pr]);
            float4 ahi = *reinterpret_cast<const float4*>(&sA[k][pr + 64]);
            float4 blo = *reinterpret_cast<const float4*>(&sX[k][dr]);
            float4 bhi = *reinterpret_cast<const float4*>(&sX[k][dr + 64]);
            unsigned long long a2[4], b2[8];
            a2[0] = pack2(alo.x, alo.y);
            a2[1] = pack2(alo.z, alo.w);
            a2[2] = pack2(ahi.x, ahi.y);
            a2[3] = pack2(ahi.z, ahi.w);
            b2[0] = dup2(blo.x); b2[1] = dup2(blo.y);
            b2[2] = dup2(blo.z); b2[3] = dup2(blo.w);
            b2[4] = dup2(bhi.x); b2[5] = dup2(bhi.y);
            b2[6] = dup2(bhi.z); b2[7] = dup2(bhi.w);
#pragma unroll
            for (int pp = 0; pp < 4; pp++)
#pragma unroll
                for (int j = 0; j < 8; j++) fma2(acc[pp][j], a2[pp], b2[j]);
        }
        __syncthreads();
    }

    // epilogue: scale by (1+ew[p]), add mask[b,p]*eb[b]
    float ebb = eb[b];
#pragma unroll
    for (int pp = 0; pp < 4; pp++) {
        int pbase = p0 + pr + ((pp & 1) * 2) + ((pp >> 1) * 64);
        float lo[8], hi[8];
#pragma unroll
        for (int j = 0; j < 8; j++) unpack2(acc[pp][j], lo[j], hi[j]);
#pragma unroll
        for (int h = 0; h < 2; h++) {
            int p = pbase + h;
            float sc = 1.0f + ew[p];
            float ba = g_mask[b * 256 + p] * ebb;
            float4 o0, o1;
            if (h == 0) {
                o0.x = lo[0] * sc + ba; o0.y = lo[1] * sc + ba;
                o0.z = lo[2] * sc + ba; o0.w = lo[3] * sc + ba;
                o1.x = lo[4] * sc + ba; o1.y = lo[5] * sc + ba;
                o1.z = lo[6] * sc + ba; o1.w = lo[7] * sc + ba;
            } else {
                o0.x = hi[0] * sc + ba; o0.y = hi[1] * sc + ba;
                o0.z = hi[2] * sc + ba; o0.w = hi[3] * sc + ba;
                o1.x = hi[4] * sc + ba; o1.y = hi[5] * sc + ba;
                o1.z = hi[6] * sc + ba; o1.w = hi[7] * sc + ba;
            }
            float* op = out + (size_t)b * 65536 + p * 256 + d0 + dr;
            *reinterpret_cast<float4*>(op) = o0;
            *reinterpret_cast<float4*>(op + 64) = o1;
        }
    }
}

// ---------------------------------------------------------------------------
extern "C" void kernel_launch(void* const* d_in, const int* in_sizes, int n_in,
                              void* d_out, int out_size) {
    const float* x    = (const float*)d_in[0];   // [B,C]
    const float* prev = (const float*)d_in[1];   // [P,D]
    const float* fw   = (const float*)d_in[2];   // [C,D]
    const float* fb   = (const float*)d_in[3];   // [1,C,D]
    const float* lew  = (const float*)d_in[4];
    const float* leb  = (const float*)d_in[5];
    const float* lcw  = (const float*)d_in[6];
    const float* lcb  = (const float*)d_in[7];
    const float* lpw  = (const float*)d_in[8];
    const float* lpb  = (const float*)d_in[9];
    const float* W    = (const float*)d_in[10];  // [D,2D]
    const float* Wb   = (const float*)d_in[11];  // [D]
    const float* ecol = (const float*)d_in[12];  // [C,D]
    const float* eprm = (const float*)d_in[13];  // [P,D]
    const float* ew   = (const float*)d_in[14];  // [P,1]
    const float* eb   = (const float*)d_in[15];  // [P]
    float* out = (float*)d_out;                  // [1,B,P,D]

    k_xemb<<<8192, 256>>>(x, fw, fb, lew, leb);
    k_prep<<<64, 256>>>(eprm, prev, lpw, lpb, ecol, lcw, lcb);
    k_gemm<0><<<dim3(8, 8), 256>>>(W, Wb, eprm);        // x_prompt
    k_gemm<1><<<dim3(8, 8), 256>>>(nullptr, nullptr, nullptr);  // logits
    k_softmax<<<256, 256>>>();
    k_main<<<dim3(2, 2, 256), 256>>>(ew, eb, out);
}

// round 8
// speedup vs baseline: 1.7294x; 1.7294x over previous
#include <cuda_runtime.h>
#include <cstdint>

#define EPS 1e-5f

// ---------------- scratch (device globals: no allocation allowed) ----------
// g_xembT: [b][d][c]  (transposed x_emb, tf32-rounded)  64 Mi floats
__device__ float g_xembT[256 * 256 * 256];
__device__ float g_xpin[256 * 512];
__device__ float g_xprompt[256 * 256];
__device__ float g_xcol[256 * 256];
__device__ float g_logits[256 * 256];
__device__ float g_mask[256 * 256];     // [p][c], tf32-rounded

// ---------------- PTX helpers ----------------------------------------------
__device__ __forceinline__ uint32_t s2u(const void* p) {
    uint32_t a;
    asm("{ .reg .u64 t; cvta.to.shared.u64 t, %1; cvt.u32.u64 %0, t; }"
        : "=r"(a) : "l"(p));
    return a;
}
__device__ __forceinline__ float to_tf32(float x) {
    float r;
    asm("cvt.rna.tf32.f32 %0, %1;" : "=f"(r) : "f"(x));
    return r;
}
__device__ __forceinline__ void cpa16(uint32_t dst, const void* gsrc) {
    asm volatile("{ .reg .u64 g; cvta.to.global.u64 g, %1;"
                 " cp.async.cg.shared.global [%0], [g], 16; }"
                 :: "r"(dst), "l"(gsrc));
}
__device__ __forceinline__ void cp_commit() {
    asm volatile("cp.async.commit_group;" ::: "memory");
}
__device__ __forceinline__ void cp_wait1() {
    asm volatile("cp.async.wait_group 1;" ::: "memory");
}
__device__ __forceinline__ void mma_tf32(float* c, const uint32_t* a,
                                         const uint32_t* b) {
    asm volatile(
        "mma.sync.aligned.m16n8k8.row.col.f32.tf32.tf32.f32 "
        "{%0,%1,%2,%3}, {%4,%5,%6,%7}, {%8,%9}, {%0,%1,%2,%3};"
        : "+f"(c[0]), "+f"(c[1]), "+f"(c[2]), "+f"(c[3])
        : "r"(a[0]), "r"(a[1]), "r"(a[2]), "r"(a[3]), "r"(b[0]), "r"(b[1]));
}

// ---------------- kernel 1: x_emb = LN(relu(fb + x*fw)) -> g_xembT[b][d][c]
// CTA = (cb = c-block of 32, bgroup of 4 b).  grid (8, 64), 256 threads.
__global__ void __launch_bounds__(256) k_xemb(const float* __restrict__ x,
                                              const float* __restrict__ fw,
                                              const float* __restrict__ fb,
                                              const float* __restrict__ lw,
                                              const float* __restrict__ lb) {
    extern __shared__ float sm[];
    float* sW = sm;                    // [32][256]
    float* sF = sm + 32 * 256;         // [32][256]
    float* sT = sm + 2 * 32 * 256;     // [32][257] padded
    float* sLw = sT + 32 * 257;        // [256]
    float* sLb = sLw + 256;            // [256]
    int tid = threadIdx.x, lane = tid & 31, w = tid >> 5;
    int cb = blockIdx.x;
    int bg = blockIdx.y;

    const float4* fw4 = reinterpret_cast<const float4*>(fw) + cb * 32 * 64;
    const float4* fb4 = reinterpret_cast<const float4*>(fb) + cb * 32 * 64;
    float4* sW4 = reinterpret_cast<float4*>(sW);
    float4* sF4 = reinterpret_cast<float4*>(sF);
#pragma unroll
    for (int t = 0; t < 8; t++) {
        int f = tid + t * 256;
        sW4[f] = fw4[f];
        sF4[f] = fb4[f];
    }
    sLw[tid] = lw[tid];
    sLb[tid] = lb[tid];
    __syncthreads();

    for (int bi = 0; bi < 4; bi++) {
        int b = bg * 4 + bi;
#pragma unroll
        for (int r = 0; r < 4; r++) {
            int c = w * 4 + r;
            float xv = x[b * 256 + cb * 32 + c];
            float v[8], s = 0.f, q = 0.f;
#pragma unroll
            for (int t = 0; t < 8; t++) {
                int d = lane + 32 * t;
                float val = fmaxf(fmaf(xv, sW[c * 256 + d], sF[c * 256 + d]), 0.f);
                v[t] = val;
                s += val;
                q += val * val;
            }
#pragma unroll
            for (int o = 16; o; o >>= 1) {
                s += __shfl_xor_sync(0xffffffffu, s, o);
                q += __shfl_xor_sync(0xffffffffu, q, o);
            }
            float mu = s * (1.f / 256.f);
            float rs = rsqrtf(q * (1.f / 256.f) - mu * mu + EPS);
#pragma unroll
            for (int t = 0; t < 8; t++) {
                int d = lane + 32 * t;
                sT[c * 257 + d] = (v[t] - mu) * rs * sLw[d] + sLb[d];
            }
        }
        __syncthreads();
        float* dst = g_xembT + (size_t)b * 65536;
#pragma unroll
        for (int i = 0; i < 32; i++) {
            int fl = tid + i * 256;
            int d = fl >> 5, c = fl & 31;  // c == lane -> 128B coalesced
            dst[d * 256 + cb * 32 + c] = to_tf32(sT[c * 257 + d]);
        }
        __syncthreads();
    }
}

// ---------------- warp-per-row LayerNorm helper (for k_prep) ----------------
__device__ __forceinline__ void ln_row_warp(const float4 v0, const float4 v1,
                                            const float* __restrict__ w,
                                            const float* __restrict__ b,
                                            float* __restrict__ dst, int lane) {
    float s = v0.x + v0.y + v0.z + v0.w + v1.x + v1.y + v1.z + v1.w;
    float q = v0.x * v0.x + v0.y * v0.y + v0.z * v0.z + v0.w * v0.w +
              v1.x * v1.x + v1.y * v1.y + v1.z * v1.z + v1.w * v1.w;
#pragma unroll
    for (int o = 16; o; o >>= 1) {
        s += __shfl_xor_sync(0xffffffffu, s, o);
        q += __shfl_xor_sync(0xffffffffu, q, o);
    }
    float mu = s * (1.0f / 256.0f);
    float rs = rsqrtf(q * (1.0f / 256.0f) - mu * mu + EPS);
    const float4* w4 = reinterpret_cast<const float4*>(w);
    const float4* b4 = reinterpret_cast<const float4*>(b);
    float4 g0 = w4[lane], g1 = w4[lane + 32];
    float4 h0 = b4[lane], h1 = b4[lane + 32];
    float4 o0, o1;
    o0.x = (v0.x - mu) * rs * g0.x + h0.x;
    o0.y = (v0.y - mu) * rs * g0.y + h0.y;
    o0.z = (v0.z - mu) * rs * g0.z + h0.z;
    o0.w = (v0.w - mu) * rs * g0.w + h0.w;
    o1.x = (v1.x - mu) * rs * g1.x + h1.x;
    o1.y = (v1.y - mu) * rs * g1.y + h1.y;
    o1.z = (v1.z - mu) * rs * g1.z + h1.z;
    o1.w = (v1.w - mu) * rs * g1.w + h1.w;
    float4* d4 = reinterpret_cast<float4*>(dst);
    d4[lane] = o0;
    d4[lane + 32] = o1;
}

// ---------------- kernel 2: LN(emb_prompt)->xpin, copy prev, LN(emb_col) ----
__global__ void __launch_bounds__(256) k_prep(const float* __restrict__ eprm,
                                              const float* __restrict__ prev,
                                              const float* __restrict__ lpw,
                                              const float* __restrict__ lpb,
                                              const float* __restrict__ ecol,
                                              const float* __restrict__ lcw,
                                              const float* __restrict__ lcb) {
    int row = blockIdx.x * 8 + (threadIdx.x >> 5);
    int lane = threadIdx.x & 31;
    if (row < 256) {
        const float4* s4 = reinterpret_cast<const float4*>(eprm) + row * 64;
        ln_row_warp(s4[lane], s4[lane + 32], lpw, lpb, g_xpin + row * 512, lane);
        const float4* p4 = reinterpret_cast<const float4*>(prev) + row * 64;
        float4* d4 = reinterpret_cast<float4*>(g_xpin + row * 512 + 256);
        d4[lane] = p4[lane];
        d4[lane + 32] = p4[lane + 32];
    } else {
        int c = row - 256;
        const float4* s4 = reinterpret_cast<const float4*>(ecol) + c * 64;
        ln_row_warp(s4[lane], s4[lane + 32], lcw, lcb, g_xcol + c * 256, lane);
    }
}

// ---------------- kernel 3: small GEMMs with register-prefetch pipeline -----
template <int MODE>
__global__ void __launch_bounds__(256) k_gemm(const float* __restrict__ Bp,
                                              const float* __restrict__ bias,
                                              const float* __restrict__ add) {
    constexpr int K = (MODE == 0) ? 512 : 256;
    const float* A = (MODE == 0) ? g_xpin : g_xprompt;
    const float* B = (MODE == 0) ? Bp : g_xcol;
    float* C = (MODE == 0) ? g_xprompt : g_logits;

    __shared__ float sA[32][65];
    __shared__ float sB[32][65];
    int tid = threadIdx.x;
    int i0 = blockIdx.y * 32, j0 = blockIdx.x * 32;
    int ty = tid >> 4, tx = tid & 15;
    float ra[8], rb[8];
#pragma unroll
    for (int t = 0; t < 8; t++) {
        int f = tid + t * 256, r = f >> 6, kk = f & 63;
        ra[t] = A[(i0 + r) * K + kk];
        rb[t] = B[(j0 + r) * K + kk];
    }
    float a00 = 0.f, a01 = 0.f, a10 = 0.f, a11 = 0.f;
    for (int kc = 0; kc < K; kc += 64) {
#pragma unroll
        for (int t = 0; t < 8; t++) {
            int f = tid + t * 256, r = f >> 6, kk = f & 63;
            sA[r][kk] = ra[t];
            sB[r][kk] = rb[t];
        }
        __syncthreads();
        if (kc + 64 < K) {
#pragma unroll
            for (int t = 0; t < 8; t++) {
                int f = tid + t * 256, r = f >> 6, kk = f & 63;
                ra[t] = A[(i0 + r) * K + kc + 64 + kk];
                rb[t] = B[(j0 + r) * K + kc + 64 + kk];
            }
        }
#pragma unroll 8
        for (int k = 0; k < 64; k++) {
            float x0 = sA[ty * 2][k], x1 = sA[ty * 2 + 1][k];
            float y0 = sB[tx * 2][k], y1 = sB[tx * 2 + 1][k];
            a00 = fmaf(x0, y0, a00);
            a01 = fmaf(x0, y1, a01);
            a10 = fmaf(x1, y0, a10);
            a11 = fmaf(x1, y1, a11);
        }
        __syncthreads();
    }
    int i = i0 + ty * 2, j = j0 + tx * 2;
    if (MODE == 0) {
        a00 += bias[j] + add[i * 256 + j];
        a01 += bias[j + 1] + add[i * 256 + j + 1];
        a10 += bias[j] + add[(i + 1) * 256 + j];
        a11 += bias[j + 1] + add[(i + 1) * 256 + j + 1];
    }
    C[i * 256 + j] = a00;
    C[i * 256 + j + 1] = a01;
    C[(i + 1) * 256 + j] = a10;
    C[(i + 1) * 256 + j + 1] = a11;
}

// ---------------- kernel 4: row softmax (emits tf32-rounded mask) -----------
__global__ void __launch_bounds__(256) k_softmax() {
    __shared__ float red[256];
    int p = blockIdx.x, c = threadIdx.x;
    float v = g_logits[p * 256 + c];
    red[c] = v;
    __syncthreads();
#pragma unroll
    for (int s = 128; s > 0; s >>= 1) {
        if (c < s) red[c] = fmaxf(red[c], red[c + s]);
        __syncthreads();
    }
    float mx = red[0];
    __syncthreads();
    float e = expf(v - mx);
    red[c] = e;
    __syncthreads();
#pragma unroll
    for (int s = 128; s > 0; s >>= 1) {
        if (c < s) red[c] += red[c + s];
        __syncthreads();
    }
    g_mask[p * 256 + c] = to_tf32(e * (1.0f / red[0]));
}

// ---------------- kernel 5: mma.sync tf32  out[b] = scale(mask @ xemb_b) ----
// CTA tile 128(p) x 128(d) per b, grid (2,2,256).  8 warps as 4(m) x 2(n),
// each warp 32x64.  K = 256 in 8 chunks of 32, double-buffered cp.async.
// smem rows padded to 36 floats -> bank = (4*row + k) % 32 -> conflict-free.
static constexpr int PAD = 36;
static constexpr int BUF_F = 2 * 128 * PAD;           // A + B, floats
static constexpr int SMEM_MAIN = 2 * BUF_F * 4;       // 73728 B

__global__ void __launch_bounds__(256, 2) k_main(const float* __restrict__ ew,
                                                 const float* __restrict__ eb,
                                                 float* __restrict__ out) {
    extern __shared__ float sm[];
    int tid = threadIdx.x;
    int b = blockIdx.z;
    int p0 = blockIdx.y * 128, d0 = blockIdx.x * 128;
    int w = tid >> 5, lane = tid & 31;
    int wm = w & 3, wn = w >> 2;
    int r = lane >> 2, c = lane & 3;

    const float* Asrc = g_mask + p0 * 256;
    const float* Bsrc = g_xembT + (size_t)b * 65536 + (size_t)d0 * 256;
    uint32_t sbase = s2u(sm);

    float acc[2][8][4];
#pragma unroll
    for (int mi = 0; mi < 2; mi++)
#pragma unroll
        for (int ni = 0; ni < 8; ni++)
#pragma unroll
            for (int j = 0; j < 4; j++) acc[mi][ni][j] = 0.f;

    // prologue: chunks 0, 1
#pragma unroll
    for (int cb = 0; cb < 2; cb++) {
        uint32_t dA = sbase + cb * BUF_F * 4;
        uint32_t dB = dA + 128 * PAD * 4;
#pragma unroll
        for (int t = 0; t < 4; t++) {
            int idx = tid + t * 256;       // 0..1023
            int row = idx >> 3, j = idx & 7;
            cpa16(dA + (row * PAD + j * 4) * 4, Asrc + row * 256 + cb * 32 + j * 4);
            cpa16(dB + (row * PAD + j * 4) * 4, Bsrc + row * 256 + cb * 32 + j * 4);
        }
        cp_commit();
    }

    for (int i = 0; i < 8; i++) {
        int buf = i & 1;
        cp_wait1();
        __syncthreads();

        const uint32_t* A = reinterpret_cast<const uint32_t*>(sm + buf * BUF_F);
        const uint32_t* Bt = A + 128 * PAD;
#pragma unroll
        for (int s = 0; s < 4; s++) {
            int k0 = s * 8;
            uint32_t af[2][4];
#pragma unroll
            for (int mi = 0; mi < 2; mi++) {
                int base = (wm * 32 + mi * 16 + r) * PAD + k0 + c;
                af[mi][0] = A[base];
                af[mi][1] = A[base + 8 * PAD];
                af[mi][2] = A[base + 4];
                af[mi][3] = A[base + 8 * PAD + 4];
            }
#pragma unroll
            for (int ni = 0; ni < 8; ni++) {
                int base = (wn * 64 + ni * 8 + r) * PAD + k0 + c;
                uint32_t bf[2] = {Bt[base], Bt[base + 4]};
                mma_tf32(acc[0][ni], af[0], bf);
                mma_tf32(acc[1][ni], af[1], bf);
            }
        }
        __syncthreads();

        if (i + 2 < 8) {
            int cb = i + 2;
            uint32_t dA = sbase + buf * BUF_F * 4;
            uint32_t dB = dA + 128 * PAD * 4;
#pragma unroll
            for (int t = 0; t < 4; t++) {
                int idx = tid + t * 256;
                int row = idx >> 3, j = idx & 7;
                cpa16(dA + (row * PAD + j * 4) * 4,
                      Asrc + row * 256 + cb * 32 + j * 4);
                cpa16(dB + (row * PAD + j * 4) * 4,
                      Bsrc + row * 256 + cb * 32 + j * 4);
            }
        }
        cp_commit();
    }

    // ---- epilogue: scale by (1+ew[p]), add mask[b,p]*eb[b], direct STG -----
    float ebb = eb[b];
#pragma unroll
    for (int mi = 0; mi < 2; mi++) {
#pragma unroll
        for (int half = 0; half < 2; half++) {
            int p = p0 + wm * 32 + mi * 16 + r + half * 8;
            float sc = 1.0f + ew[p];
            float ba = g_mask[b * 256 + p] * ebb;
            float* orow = out + (size_t)b * 65536 + (size_t)p * 256 +
                          d0 + wn * 64 + 2 * c;
#pragma unroll
            for (int ni = 0; ni < 8; ni++) {
                float2 v;
                v.x = acc[mi][ni][half * 2 + 0] * sc + ba;
                v.y = acc[mi][ni][half * 2 + 1] * sc + ba;
                *reinterpret_cast<float2*>(orow + ni * 8) = v;
            }
        }
    }
}

// ---------------------------------------------------------------------------
extern "C" void kernel_launch(void* const* d_in, const int* in_sizes, int n_in,
                              void* d_out, int out_size) {
    const float* x    = (const float*)d_in[0];   // [B,C]
    const float* prev = (const float*)d_in[1];   // [P,D]
    const float* fw   = (const float*)d_in[2];   // [C,D]
    const float* fb   = (const float*)d_in[3];   // [1,C,D]
    const float* lew  = (const float*)d_in[4];
    const float* leb  = (const float*)d_in[5];
    const float* lcw  = (const float*)d_in[6];
    const float* lcb  = (const float*)d_in[7];
    const float* lpw  = (const float*)d_in[8];
    const float* lpb  = (const float*)d_in[9];
    const float* W    = (const float*)d_in[10];  // [D,2D]
    const float* Wb   = (const float*)d_in[11];  // [D]
    const float* ecol = (const float*)d_in[12];  // [C,D]
    const float* eprm = (const float*)d_in[13];  // [P,D]
    const float* ew   = (const float*)d_in[14];  // [P,1]
    const float* eb   = (const float*)d_in[15];  // [P]
    float* out = (float*)d_out;                  // [1,B,P,D]

    const int smem_xemb = (2 * 32 * 256 + 32 * 257 + 512) * 4;  // ~100.5 KB
    cudaFuncSetAttribute(k_xemb, cudaFuncAttributeMaxDynamicSharedMemorySize,
                         smem_xemb);
    cudaFuncSetAttribute(k_main, cudaFuncAttributeMaxDynamicSharedMemorySize,
                         SMEM_MAIN);

    k_xemb<<<dim3(8, 64), 256, smem_xemb>>>(x, fw, fb, lew, leb);
    k_prep<<<64, 256>>>(eprm, prev, lpw, lpb, ecol, lcw, lcb);
    k_gemm<0><<<dim3(8, 8), 256>>>(W, Wb, eprm);                 // x_prompt
    k_gemm<1><<<dim3(8, 8), 256>>>(nullptr, nullptr, nullptr);   // logits
    k_softmax<<<256, 256>>>();
    k_main<<<dim3(2, 2, 256), 256, SMEM_MAIN>>>(ew, eb, out);
}

// round 9
// speedup vs baseline: 1.9127x; 1.1060x over previous
#include <cuda_runtime.h>
#include <cstdint>

#define EPS 1e-5f

// ---------------- scratch (device globals: no allocation allowed) ----------
// g_xembT: [b][d][c]  (transposed x_emb, tf32-rounded)  64 Mi floats
__device__ float g_xembT[256 * 256 * 256];
__device__ float g_xpin[256 * 512];
__device__ float g_xprompt[256 * 256];
__device__ float g_xcol[256 * 256];
__device__ float g_mask[256 * 256];       // [p][c], tf32-rounded
__device__ float g_part[8 * 256 * 256];   // split-K partials (reused)

// ---------------- PTX helpers ----------------------------------------------
__device__ __forceinline__ uint32_t s2u(const void* p) {
    uint32_t a;
    asm("{ .reg .u64 t; cvta.to.shared.u64 t, %1; cvt.u32.u64 %0, t; }"
        : "=r"(a) : "l"(p));
    return a;
}
__device__ __forceinline__ float to_tf32(float x) {
    float r;
    asm("cvt.rna.tf32.f32 %0, %1;" : "=f"(r) : "f"(x));
    return r;
}
__device__ __forceinline__ void cpa16(uint32_t dst, const void* gsrc) {
    asm volatile("{ .reg .u64 g; cvta.to.global.u64 g, %1;"
                 " cp.async.cg.shared.global [%0], [g], 16; }"
                 :: "r"(dst), "l"(gsrc));
}
__device__ __forceinline__ void cp_commit() {
    asm volatile("cp.async.commit_group;" ::: "memory");
}
__device__ __forceinline__ void cp_wait1() {
    asm volatile("cp.async.wait_group 1;" ::: "memory");
}
__device__ __forceinline__ void mma_tf32(float* c, const uint32_t* a,
                                         const uint32_t* b) {
    asm volatile(
        "mma.sync.aligned.m16n8k8.row.col.f32.tf32.tf32.f32 "
        "{%0,%1,%2,%3}, {%4,%5,%6,%7}, {%8,%9}, {%0,%1,%2,%3};"
        : "+f"(c[0]), "+f"(c[1]), "+f"(c[2]), "+f"(c[3])
        : "r"(a[0]), "r"(a[1]), "r"(a[2]), "r"(a[3]), "r"(b[0]), "r"(b[1]));
}

// ---------------- kernel 1: x_emb = LN(relu(fb + x*fw)) -> g_xembT[b][d][c]
__global__ void __launch_bounds__(256) k_xemb(const float* __restrict__ x,
                                              const float* __restrict__ fw,
                                              const float* __restrict__ fb,
                                              const float* __restrict__ lw,
                                              const float* __restrict__ lb) {
    extern __shared__ float sm[];
    float* sW = sm;                    // [32][256]
    float* sF = sm + 32 * 256;         // [32][256]
    float* sT = sm + 2 * 32 * 256;     // [32][257] padded
    float* sLw = sT + 32 * 257;        // [256]
    float* sLb = sLw + 256;            // [256]
    int tid = threadIdx.x, lane = tid & 31, w = tid >> 5;
    int cb = blockIdx.x;
    int bg = blockIdx.y;

    const float4* fw4 = reinterpret_cast<const float4*>(fw) + cb * 32 * 64;
    const float4* fb4 = reinterpret_cast<const float4*>(fb) + cb * 32 * 64;
    float4* sW4 = reinterpret_cast<float4*>(sW);
    float4* sF4 = reinterpret_cast<float4*>(sF);
#pragma unroll
    for (int t = 0; t < 8; t++) {
        int f = tid + t * 256;
        sW4[f] = fw4[f];
        sF4[f] = fb4[f];
    }
    sLw[tid] = lw[tid];
    sLb[tid] = lb[tid];
    __syncthreads();

    for (int bi = 0; bi < 4; bi++) {
        int b = bg * 4 + bi;
#pragma unroll
        for (int r = 0; r < 4; r++) {
            int c = w * 4 + r;
            float xv = x[b * 256 + cb * 32 + c];
            float v[8], s = 0.f, q = 0.f;
#pragma unroll
            for (int t = 0; t < 8; t++) {
                int d = lane + 32 * t;
                float val = fmaxf(fmaf(xv, sW[c * 256 + d], sF[c * 256 + d]), 0.f);
                v[t] = val;
                s += val;
                q += val * val;
            }
#pragma unroll
            for (int o = 16; o; o >>= 1) {
                s += __shfl_xor_sync(0xffffffffu, s, o);
                q += __shfl_xor_sync(0xffffffffu, q, o);
            }
            float mu = s * (1.f / 256.f);
            float rs = rsqrtf(q * (1.f / 256.f) - mu * mu + EPS);
#pragma unroll
            for (int t = 0; t < 8; t++) {
                int d = lane + 32 * t;
                sT[c * 257 + d] = (v[t] - mu) * rs * sLw[d] + sLb[d];
            }
        }
        __syncthreads();
        float* dst = g_xembT + (size_t)b * 65536;
#pragma unroll
        for (int i = 0; i < 32; i++) {
            int fl = tid + i * 256;
            int d = fl >> 5, c = fl & 31;  // c == lane -> 128B coalesced
            dst[d * 256 + cb * 32 + c] = to_tf32(sT[c * 257 + d]);
        }
        __syncthreads();
    }
}

// ---------------- warp-per-row LayerNorm helper (for k_prep) ----------------
__device__ __forceinline__ void ln_row_warp(const float4 v0, const float4 v1,
                                            const float* __restrict__ w,
                                            const float* __restrict__ b,
                                            float* __restrict__ dst, int lane) {
    float s = v0.x + v0.y + v0.z + v0.w + v1.x + v1.y + v1.z + v1.w;
    float q = v0.x * v0.x + v0.y * v0.y + v0.z * v0.z + v0.w * v0.w +
              v1.x * v1.x + v1.y * v1.y + v1.z * v1.z + v1.w * v1.w;
#pragma unroll
    for (int o = 16; o; o >>= 1) {
        s += __shfl_xor_sync(0xffffffffu, s, o);
        q += __shfl_xor_sync(0xffffffffu, q, o);
    }
    float mu = s * (1.0f / 256.0f);
    float rs = rsqrtf(q * (1.0f / 256.0f) - mu * mu + EPS);
    const float4* w4 = reinterpret_cast<const float4*>(w);
    const float4* b4 = reinterpret_cast<const float4*>(b);
    float4 g0 = w4[lane], g1 = w4[lane + 32];
    float4 h0 = b4[lane], h1 = b4[lane + 32];
    float4 o0, o1;
    o0.x = (v0.x - mu) * rs * g0.x + h0.x;
    o0.y = (v0.y - mu) * rs * g0.y + h0.y;
    o0.z = (v0.z - mu) * rs * g0.z + h0.z;
    o0.w = (v0.w - mu) * rs * g0.w + h0.w;
    o1.x = (v1.x - mu) * rs * g1.x + h1.x;
    o1.y = (v1.y - mu) * rs * g1.y + h1.y;
    o1.z = (v1.z - mu) * rs * g1.z + h1.z;
    o1.w = (v1.w - mu) * rs * g1.w + h1.w;
    float4* d4 = reinterpret_cast<float4*>(dst);
    d4[lane] = o0;
    d4[lane + 32] = o1;
}

// ---------------- kernel 2: LN(emb_prompt)->xpin, copy prev, LN(emb_col) ----
__global__ void __launch_bounds__(256) k_prep(const float* __restrict__ eprm,
                                              const float* __restrict__ prev,
                                              const float* __restrict__ lpw,
                                              const float* __restrict__ lpb,
                                              const float* __restrict__ ecol,
                                              const float* __restrict__ lcw,
                                              const float* __restrict__ lcb) {
    int row = blockIdx.x * 8 + (threadIdx.x >> 5);
    int lane = threadIdx.x & 31;
    if (row < 256) {
        const float4* s4 = reinterpret_cast<const float4*>(eprm) + row * 64;
        ln_row_warp(s4[lane], s4[lane + 32], lpw, lpb, g_xpin + row * 512, lane);
        const float4* p4 = reinterpret_cast<const float4*>(prev) + row * 64;
        float4* d4 = reinterpret_cast<float4*>(g_xpin + row * 512 + 256);
        d4[lane] = p4[lane];
        d4[lane + 32] = p4[lane + 32];
    } else {
        int c = row - 256;
        const float4* s4 = reinterpret_cast<const float4*>(ecol) + c * 64;
        ln_row_warp(s4[lane], s4[lane + 32], lcw, lcb, g_xcol + c * 256, lane);
    }
}

// ---------------- kernel 3: split-K small GEMM  part[z][i][j] += A·B^T ------
// C[i,j] = sum_k A[i,k]*B[j,k].  Tile 64x64, thread 4x4, grid (4,4,SPLIT).
// sA row-major [64][36] (broadcast scalar loads); sBT k-major [32][68] with
// column swizzle col ^ ((k>>2)<<2): conflict-free STS scatter + 2-phase LDS.128.
template <int K, int KC>
__global__ void __launch_bounds__(256) k_sgemm(const float* __restrict__ A,
                                               const float* __restrict__ B,
                                               float* __restrict__ part) {
    __shared__ float sA[64][36];
    __shared__ float sBT[32][68];
    int tid = threadIdx.x;
    int j0 = blockIdx.x * 64, i0 = blockIdx.y * 64;
    int kz = blockIdx.z;
    int ty = tid >> 4, tx = tid & 15;
    float acc[4][4] = {};

    for (int ch = 0; ch < KC / 32; ch++) {
        int kb = kz * KC + ch * 32;
#pragma unroll
        for (int s = 0; s < 2; s++) {
            int task = tid + s * 256;
            int row = task >> 3, kq = task & 7;
            float4 va = *reinterpret_cast<const float4*>(
                &A[(size_t)(i0 + row) * K + kb + kq * 4]);
            *reinterpret_cast<float4*>(&sA[row][kq * 4]) = va;
            float4 vb = *reinterpret_cast<const float4*>(
                &B[(size_t)(j0 + row) * K + kb + kq * 4]);
            int cs = row ^ (kq << 2);
            sBT[kq * 4 + 0][cs] = vb.x;
            sBT[kq * 4 + 1][cs] = vb.y;
            sBT[kq * 4 + 2][cs] = vb.z;
            sBT[kq * 4 + 3][cs] = vb.w;
        }
        __syncthreads();
#pragma unroll
        for (int k = 0; k < 32; k++) {
            float a[4];
#pragma unroll
            for (int t = 0; t < 4; t++) a[t] = sA[ty * 4 + t][k];
            int cs = (tx * 4) ^ ((k >> 2) << 2);
            float4 b4 = *reinterpret_cast<const float4*>(&sBT[k][cs]);
#pragma unroll
            for (int t = 0; t < 4; t++) {
                acc[t][0] = fmaf(a[t], b4.x, acc[t][0]);
                acc[t][1] = fmaf(a[t], b4.y, acc[t][1]);
                acc[t][2] = fmaf(a[t], b4.z, acc[t][2]);
                acc[t][3] = fmaf(a[t], b4.w, acc[t][3]);
            }
        }
        __syncthreads();
    }
    float* dst = part + (size_t)kz * 65536;
#pragma unroll
    for (int t = 0; t < 4; t++) {
        float4 v = make_float4(acc[t][0], acc[t][1], acc[t][2], acc[t][3]);
        *reinterpret_cast<float4*>(&dst[(i0 + ty * 4 + t) * 256 + j0 + tx * 4]) = v;
    }
}

// ---------------- kernel 4a: reduce gemm0 partials + bias + emb_prompt ------
__global__ void __launch_bounds__(256) k_red0(const float* __restrict__ Wb,
                                              const float* __restrict__ eprm) {
    int idx = blockIdx.x * 256 + threadIdx.x;  // float4 index, 16384 total
    const float4* p4 = reinterpret_cast<const float4*>(g_part);
    float4 s = p4[idx];
#pragma unroll
    for (int z = 1; z < 8; z++) {
        float4 v = p4[z * 16384 + idx];
        s.x += v.x; s.y += v.y; s.z += v.z; s.w += v.w;
    }
    float4 wb = reinterpret_cast<const float4*>(Wb)[idx & 63];
    float4 ep = reinterpret_cast<const float4*>(eprm)[idx];
    s.x += wb.x + ep.x; s.y += wb.y + ep.y;
    s.z += wb.z + ep.z; s.w += wb.w + ep.w;
    reinterpret_cast<float4*>(g_xprompt)[idx] = s;
}

// ---------------- kernel 4b: reduce gemm1 partials + row softmax ------------
__global__ void __launch_bounds__(256) k_red1s() {
    __shared__ float red[256];
    int p = blockIdx.x, c = threadIdx.x;
    float v = 0.f;
#pragma unroll
    for (int z = 0; z < 8; z++) v += g_part[z * 65536 + p * 256 + c];
    red[c] = v;
    __syncthreads();
#pragma unroll
    for (int s = 128; s > 0; s >>= 1) {
        if (c < s) red[c] = fmaxf(red[c], red[c + s]);
        __syncthreads();
    }
    float mx = red[0];
    __syncthreads();
    float e = expf(v - mx);
    red[c] = e;
    __syncthreads();
#pragma unroll
    for (int s = 128; s > 0; s >>= 1) {
        if (c < s) red[c] += red[c + s];
        __syncthreads();
    }
    g_mask[p * 256 + c] = to_tf32(e * (1.0f / red[0]));
}

// ---------------- kernel 5: mma.sync tf32  out[b] = scale(mask @ xemb_b) ----
static constexpr int PAD = 36;
static constexpr int BUF_F = 2 * 128 * PAD;           // A + B, floats
static constexpr int SMEM_MAIN = 2 * BUF_F * 4;       // 73728 B

__global__ void __launch_bounds__(256, 2) k_main(const float* __restrict__ ew,
                                                 const float* __restrict__ eb,
                                                 float* __restrict__ out) {
    extern __shared__ float sm[];
    int tid = threadIdx.x;
    int b = blockIdx.z;
    int p0 = blockIdx.y * 128, d0 = blockIdx.x * 128;
    int w = tid >> 5, lane = tid & 31;
    int wm = w & 3, wn = w >> 2;
    int r = lane >> 2, c = lane & 3;

    const float* Asrc = g_mask + p0 * 256;
    const float* Bsrc = g_xembT + (size_t)b * 65536 + (size_t)d0 * 256;
    uint32_t sbase = s2u(sm);

    float acc[2][8][4];
#pragma unroll
    for (int mi = 0; mi < 2; mi++)
#pragma unroll
        for (int ni = 0; ni < 8; ni++)
#pragma unroll
            for (int j = 0; j < 4; j++) acc[mi][ni][j] = 0.f;

#pragma unroll
    for (int cb = 0; cb < 2; cb++) {
        uint32_t dA = sbase + cb * BUF_F * 4;
        uint32_t dB = dA + 128 * PAD * 4;
#pragma unroll
        for (int t = 0; t < 4; t++) {
            int idx = tid + t * 256;
            int row = idx >> 3, j = idx & 7;
            cpa16(dA + (row * PAD + j * 4) * 4, Asrc + row * 256 + cb * 32 + j * 4);
            cpa16(dB + (row * PAD + j * 4) * 4, Bsrc + row * 256 + cb * 32 + j * 4);
        }
        cp_commit();
    }

    for (int i = 0; i < 8; i++) {
        int buf = i & 1;
        cp_wait1();
        __syncthreads();

        const uint32_t* A = reinterpret_cast<const uint32_t*>(sm + buf * BUF_F);
        const uint32_t* Bt = A + 128 * PAD;
#pragma unroll
        for (int s = 0; s < 4; s++) {
            int k0 = s * 8;
            uint32_t af[2][4];
#pragma unroll
            for (int mi = 0; mi < 2; mi++) {
                int base = (wm * 32 + mi * 16 + r) * PAD + k0 + c;
                af[mi][0] = A[base];
                af[mi][1] = A[base + 8 * PAD];
                af[mi][2] = A[base + 4];
                af[mi][3] = A[base + 8 * PAD + 4];
            }
#pragma unroll
            for (int ni = 0; ni < 8; ni++) {
                int base = (wn * 64 + ni * 8 + r) * PAD + k0 + c;
                uint32_t bf[2] = {Bt[base], Bt[base + 4]};
                mma_tf32(acc[0][ni], af[0], bf);
                mma_tf32(acc[1][ni], af[1], bf);
            }
        }
        __syncthreads();

        if (i + 2 < 8) {
            int cb = i + 2;
            uint32_t dA = sbase + buf * BUF_F * 4;
            uint32_t dB = dA + 128 * PAD * 4;
#pragma unroll
            for (int t = 0; t < 4; t++) {
                int idx = tid + t * 256;
                int row = idx >> 3, j = idx & 7;
                cpa16(dA + (row * PAD + j * 4) * 4,
                      Asrc + row * 256 + cb * 32 + j * 4);
                cpa16(dB + (row * PAD + j * 4) * 4,
                      Bsrc + row * 256 + cb * 32 + j * 4);
            }
        }
        cp_commit();
    }

    float ebb = eb[b];
#pragma unroll
    for (int mi = 0; mi < 2; mi++) {
#pragma unroll
        for (int half = 0; half < 2; half++) {
            int p = p0 + wm * 32 + mi * 16 + r + half * 8;
            float sc = 1.0f + ew[p];
            float ba = g_mask[b * 256 + p] * ebb;
            float* orow = out + (size_t)b * 65536 + (size_t)p * 256 +
                          d0 + wn * 64 + 2 * c;
#pragma unroll
            for (int ni = 0; ni < 8; ni++) {
                float2 v;
                v.x = acc[mi][ni][half * 2 + 0] * sc + ba;
                v.y = acc[mi][ni][half * 2 + 1] * sc + ba;
                *reinterpret_cast<float2*>(orow + ni * 8) = v;
            }
        }
    }
}

// ---------------------------------------------------------------------------
extern "C" void kernel_launch(void* const* d_in, const int* in_sizes, int n_in,
                              void* d_out, int out_size) {
    const float* x    = (const float*)d_in[0];   // [B,C]
    const float* prev = (const float*)d_in[1];   // [P,D]
    const float* fw   = (const float*)d_in[2];   // [C,D]
    const float* fb   = (const float*)d_in[3];   // [1,C,D]
    const float* lew  = (const float*)d_in[4];
    const float* leb  = (const float*)d_in[5];
    const float* lcw  = (const float*)d_in[6];
    const float* lcb  = (const float*)d_in[7];
    const float* lpw  = (const float*)d_in[8];
    const float* lpb  = (const float*)d_in[9];
    const float* W    = (const float*)d_in[10];  // [D,2D]
    const float* Wb   = (const float*)d_in[11];  // [D]
    const float* ecol = (const float*)d_in[12];  // [C,D]
    const float* eprm = (const float*)d_in[13];  // [P,D]
    const float* ew   = (const float*)d_in[14];  // [P,1]
    const float* eb   = (const float*)d_in[15];  // [P]
    float* out = (float*)d_out;                  // [1,B,P,D]

    float* d_xpin;    cudaGetSymbolAddress((void**)&d_xpin, g_xpin);
    float* d_xprompt; cudaGetSymbolAddress((void**)&d_xprompt, g_xprompt);
    float* d_xcol;    cudaGetSymbolAddress((void**)&d_xcol, g_xcol);
    float* d_part;    cudaGetSymbolAddress((void**)&d_part, g_part);

    const int smem_xemb = (2 * 32 * 256 + 32 * 257 + 512) * 4;  // ~100.5 KB
    cudaFuncSetAttribute(k_xemb, cudaFuncAttributeMaxDynamicSharedMemorySize,
                         smem_xemb);
    cudaFuncSetAttribute(k_main, cudaFuncAttributeMaxDynamicSharedMemorySize,
                         SMEM_MAIN);

    k_xemb<<<dim3(8, 64), 256, smem_xemb>>>(x, fw, fb, lew, leb);
    k_prep<<<64, 256>>>(eprm, prev, lpw, lpb, ecol, lcw, lcb);
    k_sgemm<512, 64><<<dim3(4, 4, 8), 256>>>(d_xpin, W, d_part);      // gemm0
    k_red0<<<64, 256>>>(Wb, eprm);                                    // x_prompt
    k_sgemm<256, 32><<<dim3(4, 4, 8), 256>>>(d_xprompt, d_xcol, d_part); // gemm1
    k_red1s<<<256, 256>>>();                                          // softmax
    k_main<<<dim3(2, 2, 256), 256, SMEM_MAIN>>>(ew, eb, out);
}